// round 10
// baseline (speedup 1.0000x reference)
#include <cuda_runtime.h>

// CIF: continuous integrate-and-fire.
// hidden [B,T,H] f32, alphas [B,T] f32, target_lengths [B] i32 -> out [B,L,H] f32.
#define BB 32
#define TT 2000
#define HH 512
#define LL 256
#define CHUNK 32
#define NCHUNK 63             // ceil(2000/32) (tail padded with a=0, never fires)
#define NF4 500               // float4s per alpha row

// Scratch (no device allocation allowed -> __device__ globals).
__device__ float  g_scale[BB];        // per-batch alpha rescale factor
__device__ int2   g_chk[NCHUNK * BB]; // per-chunk checkpoint: (bits(integ), k)
__device__ int2   g_tok[BB * LL];     // (fire time t, bits(cur)) per token
__device__ int    g_ntok[BB];         // number of emitted tokens (<= LL)

// One CIF step, pinned to the minimal SASS chain:
// FADD -> FSETP -> SELP (pred-as-data) = 12 cyc; k-update off-chain.
__device__ __forceinline__ void cif_step(float a, float& integ, int& k)
{
    float sm1; int f;
    asm("{\n\t"
        ".reg .pred p;\n\t"
        "add.f32 %0, %0, %4;\n\t"            // integ += a            (chain)
        "setp.ge.f32 p, %0, 0f3F733333;\n\t" // p = integ >= 0.95f    (chain)
        "add.f32 %2, %0, 0fBF800000;\n\t"    // sm1 = integ - 1.0f    (parallel)
        "selp.f32 %0, %2, %0, p;\n\t"        // integ = p ? sm1 : .   (chain)
        "selp.b32 %3, 1, 0, p;\n\t"          // off-chain
        "add.s32 %1, %1, %3;\n\t"            // off-chain
        "}"
        : "+f"(integ), "+r"(k), "=f"(sm1), "=r"(f)
        : "f"(a));
}

// ---------------------------------------------------------------------------
// K1: per-batch double sum -> f32 scale. One CTA per batch, smem tree.
// ---------------------------------------------------------------------------
__global__ void cif_sum_kernel(const float* __restrict__ alphas,
                               const int*   __restrict__ tlen)
{
    const int b = blockIdx.x;
    __shared__ double red[256];
    const int i = threadIdx.x;

    const float* __restrict__ ab = alphas + (size_t)b * TT;
    double s = 0.0;
    for (int t = i; t < TT; t += 256) s += (double)ab[t];
    red[i] = s;
    __syncthreads();
    #pragma unroll
    for (int o = 128; o > 0; o >>= 1) {
        if (i < o) red[i] += red[i + o];
        __syncthreads();
    }
    if (i == 0) g_scale[b] = (float)tlen[b] / (float)red[0];
}

// ---------------------------------------------------------------------------
// K2: 1-warp serial scan, lane b = batch b. Pure pinned chain; pre-scaled
// alphas loaded chunk-double-buffered (float4, per-lane own row). One
// checkpoint STG.64 per 32 steps.
// ---------------------------------------------------------------------------
__global__ void cif_scan(const float* __restrict__ alphas)
{
    const int b = threadIdx.x;                 // 0..31
    const float scale = g_scale[b];

    const float4* __restrict__ ap4 =
        reinterpret_cast<const float4*>(alphas + (size_t)b * TT);

    float bufA[CHUNK], bufB[CHUNK];

    #define LOADCHUNK(BUF, C)                                                  \
        _Pragma("unroll")                                                      \
        for (int j = 0; j < 8; j++) {                                          \
            const int idx = (C) * 8 + j;                                       \
            const float4 v = (idx < NF4) ? ap4[idx]                            \
                                         : make_float4(0.f, 0.f, 0.f, 0.f);    \
            (BUF)[j * 4 + 0] = v.x * scale; (BUF)[j * 4 + 1] = v.y * scale;    \
            (BUF)[j * 4 + 2] = v.z * scale; (BUF)[j * 4 + 3] = v.w * scale;    \
        }

    float integ = 0.0f;
    int   k     = 0;

    #define PROCESS(BUF, C)                                                    \
        g_chk[(C) * BB + b] = make_int2(__float_as_int(integ), k);             \
        _Pragma("unroll")                                                      \
        for (int i = 0; i < CHUNK; i++) cif_step((BUF)[i], integ, k);

    LOADCHUNK(bufA, 0)
    for (int c = 0; c < NCHUNK; c += 2) {
        LOADCHUNK(bufB, c + 1)
        PROCESS(bufA, c)
        LOADCHUNK(bufA, c + 2)
        if (c + 1 < NCHUNK) PROCESS(bufB, c + 1)
    }
    #undef PROCESS
    #undef LOADCHUNK

    g_ntok[b] = (k < LL) ? k : LL;
}

// ---------------------------------------------------------------------------
// K3: parallel expand. Thread (chunk c, batch b) replays its 32 steps from
// the checkpoint with IDENTICAL FP ops -> identical fire decisions -> writes
// token records. 2016 independent threads.
// ---------------------------------------------------------------------------
__global__ void cif_expand(const float* __restrict__ alphas)
{
    const int c = blockIdx.x;                  // 0..62
    const int b = threadIdx.x;                 // 0..31

    const int2 rec = g_chk[c * BB + b];
    float integ = __int_as_float(rec.x);
    int   k     = rec.y;
    const float scale = g_scale[b];
    int2* __restrict__ tok = g_tok + b * LL;

    const float4* __restrict__ ap4 =
        reinterpret_cast<const float4*>(alphas + (size_t)b * TT);

    float av[CHUNK];
    #pragma unroll
    for (int j = 0; j < 8; j++) {
        const int idx = c * 8 + j;
        const float4 v = (idx < NF4) ? ap4[idx] : make_float4(0.f, 0.f, 0.f, 0.f);
        av[j * 4 + 0] = v.x * scale; av[j * 4 + 1] = v.y * scale;
        av[j * 4 + 2] = v.z * scale; av[j * 4 + 3] = v.w * scale;
    }

    const int tbase = c * CHUNK;
    #pragma unroll
    for (int i = 0; i < CHUNK; i++) {
        const float a    = av[i];
        const float cur  = 1.0f - integ;       // dist_completion (pre-add)
        const float snew = integ + a;
        const bool  fire = (snew >= 0.95f);
        if (fire) {
            if (k < LL) tok[k] = make_int2(tbase + i, __float_as_int(cur));
            k++;
        }
        integ = fire ? (snew - 1.0f) : snew;
    }
}

// ---------------------------------------------------------------------------
// K4 (gather): segmented weighted reduction of hidden -> out[b,k,:].
// Grid (L, B); 128 threads; thread owns one float4 (H=512). Boundary frames
// peeled; interior branch-free, unroll x16, dual accumulators for ILP.
// wfirst (remainds of previous fire) recomputed bit-exactly as a*scale - cur.
// ---------------------------------------------------------------------------
__global__ void cif_gather_kernel(const float* __restrict__ hidden,
                                  const float* __restrict__ alphas,
                                  float*       __restrict__ out)
{
    const int k   = blockIdx.x;
    const int b   = blockIdx.y;
    const int tid = threadIdx.x;

    float4 acc0 = make_float4(0.f, 0.f, 0.f, 0.f);
    float4 acc1 = make_float4(0.f, 0.f, 0.f, 0.f);

    const int ntok = g_ntok[b];
    if (k < ntok) {
        const int2  tk    = g_tok[b * LL + k];
        const int   t1    = tk.x;
        const float wlast = __int_as_float(tk.y);
        const float scale = g_scale[b];
        const float* __restrict__ ap = alphas + (size_t)b * TT;
        const float4* __restrict__ hbase =
            reinterpret_cast<const float4*>(hidden + (size_t)b * TT * HH) + tid;

        int tstart;
        if (k == 0) {
            tstart = 0;
        } else {
            const int2  tp      = g_tok[b * LL + k - 1];
            const int   t0      = tp.x;
            const float curprev = __int_as_float(tp.y);
            const float wfirst  = ap[t0] * scale - curprev;   // == remainds (bit-exact)
            const float4 h0 = hbase[(size_t)t0 * (HH / 4)];
            acc0.x = wfirst * h0.x; acc0.y = wfirst * h0.y;
            acc0.z = wfirst * h0.z; acc0.w = wfirst * h0.w;
            tstart = t0 + 1;
        }

        int t = tstart;
        // 2-wide interior: independent load+acc streams.
        for (; t + 1 < t1; t += 2) {
            const float  w0 = ap[t] * scale;
            const float  w1 = ap[t + 1] * scale;
            const float4 h0 = hbase[(size_t)t * (HH / 4)];
            const float4 h1 = hbase[(size_t)(t + 1) * (HH / 4)];
            acc0.x += w0 * h0.x; acc0.y += w0 * h0.y;
            acc0.z += w0 * h0.z; acc0.w += w0 * h0.w;
            acc1.x += w1 * h1.x; acc1.y += w1 * h1.y;
            acc1.z += w1 * h1.z; acc1.w += w1 * h1.w;
        }
        if (t < t1) {
            const float  w = ap[t] * scale;
            const float4 h = hbase[(size_t)t * (HH / 4)];
            acc0.x += w * h.x; acc0.y += w * h.y;
            acc0.z += w * h.z; acc0.w += w * h.w;
        }

        {
            const float4 h = hbase[(size_t)t1 * (HH / 4)];
            acc1.x += wlast * h.x; acc1.y += wlast * h.y;
            acc1.z += wlast * h.z; acc1.w += wlast * h.w;
        }
    }

    acc0.x += acc1.x; acc0.y += acc1.y; acc0.z += acc1.z; acc0.w += acc1.w;
    reinterpret_cast<float4*>(out + (size_t)(b * LL + k) * HH)[tid] = acc0;
}

// ---------------------------------------------------------------------------
extern "C" void kernel_launch(void* const* d_in, const int* in_sizes, int n_in,
                              void* d_out, int out_size)
{
    const float* hidden = (const float*)d_in[0];   // [B,T,H]
    const float* alphas = (const float*)d_in[1];   // [B,T]
    const int*   tlen   = (const int*)  d_in[2];   // [B]
    float*       out    = (float*)d_out;           // [B,L,H]

    cif_sum_kernel<<<BB, 256>>>(alphas, tlen);
    cif_scan<<<1, 32>>>(alphas);
    cif_expand<<<NCHUNK, 32>>>(alphas);

    dim3 grid(LL, BB);
    cif_gather_kernel<<<grid, 128>>>(hidden, alphas, out);
}